// round 16
// baseline (speedup 1.0000x reference)
#include <cuda_runtime.h>
#include <cuda_bf16.h>
#include <cstdint>

#define B_ 2
#define T_ 2048
#define E_ 2048
#define H_ 32
#define D_ 64
#define THREE_E (3 * E_)

// Scratch (no allocs allowed anywhere).
__device__ float g_vbuf[(size_t)B_ * T_ * E_];
__device__ float g_att[(size_t)B_ * T_ * E_];
__device__ float g_rx[(size_t)B_ * T_ * E_];
__device__ float g_rwq[(size_t)E_ * THREE_E];
__device__ float g_rwo[(size_t)E_ * E_];
#define SPLN ((size_t)B_ * H_ * T_ * 32)
__device__ uint32_t g_QH[SPLN], g_QL[SPLN];
__device__ uint32_t g_KH[SPLN], g_KL[SPLN];
__device__ uint32_t g_VH[SPLN], g_VL[SPLN];

// ---------------------------------------------------------------------------
// helpers
// ---------------------------------------------------------------------------
__device__ __forceinline__ uint32_t smem_u32(const void* p) {
    uint32_t a;
    asm("{ .reg .u64 t; cvta.to.shared.u64 t, %1; cvt.u32.u64 %0, t; }" : "=r"(a) : "l"(p));
    return a;
}
#define CP_ASYNC16(dst, src) \
    asm volatile("cp.async.cg.shared.global [%0], [%1], 16;" :: "r"(dst), "l"(src))
#define CP_COMMIT() asm volatile("cp.async.commit_group;" ::: "memory")
#define CP_WAITG(n) asm volatile("cp.async.wait_group %0;" :: "n"(n) : "memory")

#define LDSM_X4(r, a)                                                            \
    asm volatile("ldmatrix.sync.aligned.m8n8.x4.shared.b16 {%0,%1,%2,%3}, [%4];" \
        : "=r"((r)[0]), "=r"((r)[1]), "=r"((r)[2]), "=r"((r)[3]) : "r"(a))

__device__ __forceinline__ uint32_t f2tf32(float x) {
    uint32_t r;
    asm("cvt.rna.tf32.f32 %0, %1;" : "=r"(r) : "f"(x));
    return r;
}

__device__ __forceinline__ void mma_tf32(float* c, const uint32_t* a, const uint32_t* b) {
    asm volatile(
        "mma.sync.aligned.m16n8k8.row.col.f32.tf32.tf32.f32 "
        "{%0,%1,%2,%3}, {%4,%5,%6,%7}, {%8,%9}, {%0,%1,%2,%3};"
        : "+f"(c[0]), "+f"(c[1]), "+f"(c[2]), "+f"(c[3])
        : "r"(a[0]), "r"(a[1]), "r"(a[2]), "r"(a[3]), "r"(b[0]), "r"(b[1]));
}

__device__ __forceinline__ void mma_bf16(float* c, const uint32_t* a, uint32_t b0, uint32_t b1) {
    asm volatile(
        "mma.sync.aligned.m16n8k16.row.col.f32.bf16.bf16.f32 "
        "{%0,%1,%2,%3}, {%4,%5,%6,%7}, {%8,%9}, {%0,%1,%2,%3};"
        : "+f"(c[0]), "+f"(c[1]), "+f"(c[2]), "+f"(c[3])
        : "r"(a[0]), "r"(a[1]), "r"(a[2]), "r"(a[3]), "r"(b0), "r"(b1));
}

__device__ __forceinline__ void split2f(float x, float y, uint32_t& hi, uint32_t& lo) {
    uint32_t h;
    asm("cvt.rn.bf16x2.f32 %0, %1, %2;" : "=r"(h) : "f"(y), "f"(x));
    float hx, hy;
    asm("{ .reg .b16 a, b;\n\t"
        "mov.b32 {a, b}, %2;\n\t"
        "cvt.f32.bf16 %0, a;\n\t"
        "cvt.f32.bf16 %1, b;\n\t}"
        : "=f"(hx), "=f"(hy) : "r"(h));
    uint32_t l;
    float rx = x - hx, ry = y - hy;
    asm("cvt.rn.bf16x2.f32 %0, %1, %2;" : "=r"(l) : "f"(ry), "f"(rx));
    hi = h; lo = l;
}

// ---------------------------------------------------------------------------
// Pre-round fp32 -> tf32 bit patterns
// ---------------------------------------------------------------------------
__global__ void round_tf32(const float4* __restrict__ in, float4* __restrict__ out, int n4) {
    int i = blockIdx.x * blockDim.x + threadIdx.x;
    if (i < n4) {
        float4 v = in[i];
        float4 r;
        r.x = __uint_as_float(f2tf32(v.x));
        r.y = __uint_as_float(f2tf32(v.y));
        r.z = __uint_as_float(f2tf32(v.z));
        r.w = __uint_as_float(f2tf32(v.w));
        out[i] = r;
    }
}

// ---------------------------------------------------------------------------
// prep_v
// ---------------------------------------------------------------------------
__global__ __launch_bounds__(128)
void prep_v(const float* __restrict__ V,
            uint32_t* __restrict__ VH, uint32_t* __restrict__ VL) {
    const int tid = threadIdx.x;
    const int tb = blockIdx.x, bh = blockIdx.y;
    const int b = bh >> 5, h = bh & 31;
    const float* basep = V + (size_t)b * T_ * E_ + h * 64;
    const int kp = tid & 31;
    for (int d = tid >> 5; d < 64; d += 4) {
        const float* pv = basep + (size_t)(tb * 64 + 2 * kp) * E_ + d;
        uint32_t hi, lo;
        split2f(pv[0], pv[E_], hi, lo);
        const size_t oi = ((size_t)bh * 64 + d) * (T_ / 2) + tb * 32 + kp;
        VH[oi] = hi; VL[oi] = lo;
    }
}

// ---------------------------------------------------------------------------
// tf32 tensor-core GEMM, PERSISTENT-CTA tile loop (BK=32, 3 stages).
// MODE 0: plain store.  MODE 1: fused QKV epilogue.
// ---------------------------------------------------------------------------
#define BM 128
#define BN 128
#define BK 32
#define APAD 36
#define BPAD 136
#define NTHR 256
#define STAGES 3
#define PERSIST_CTAS 296

struct SmemTile {
    float As[BM][APAD];
    float Bs[BK][BPAD];
};
#define GEMM_SMEM (STAGES * (int)sizeof(SmemTile))

__device__ __forceinline__ void gemm_load_tile(SmemTile* st,
                                               const float* __restrict__ Ab,
                                               const float* __restrict__ Wb,
                                               int K, int N, int k0, int tid) {
#pragma unroll
    for (int it = 0; it < 4; it++) {
        int idx = tid + NTHR * it;
        int m = idx >> 3, kc = idx & 7;
        CP_ASYNC16(smem_u32(&st->As[m][kc * 4]), Ab + (size_t)m * K + k0 + kc * 4);
    }
#pragma unroll
    for (int it = 0; it < 4; it++) {
        int idx = tid + NTHR * it;
        int k = idx >> 5, c = idx & 31;
        CP_ASYNC16(smem_u32(&st->Bs[k][c * 4]), Wb + (size_t)(k0 + k) * N + c * 4);
    }
    CP_COMMIT();
}

template <int MODE>
__global__ __launch_bounds__(NTHR, 2)
void mma_gemm(int M, int N, int K,
              const float* __restrict__ A,
              const float* __restrict__ W,
              const float* __restrict__ bias,
              float* __restrict__ C,
              uint32_t* __restrict__ QHo, uint32_t* __restrict__ QLo,
              uint32_t* __restrict__ KHo, uint32_t* __restrict__ KLo,
              float* __restrict__ Vout) {
    extern __shared__ SmemTile sm[];

    const int tid = threadIdx.x;
    const int wid = tid >> 5, lane = tid & 31;
    const int wm = wid >> 2, wn = wid & 3;
    const int g = lane >> 2, t = lane & 3;

    const uint32_t lmOff = ((uint32_t)(wm * 64 + (lane & 15)) * APAD) * 4u
                         + ((uint32_t)(lane >> 4)) * 16u;

    const int ntx = N / BN;
    const int totalTiles = (M / BM) * ntx;
    const int NT = K / BK;

    for (int tile = blockIdx.x; tile < totalTiles; tile += gridDim.x) {
        const int m0 = (tile / ntx) * BM;
        const int n0 = (tile % ntx) * BN;

        const float* Ab = A + (size_t)m0 * K;
        const float* Wb = W + n0;

        float acc[4][4][4];
#pragma unroll
        for (int i = 0; i < 4; i++)
#pragma unroll
            for (int j = 0; j < 4; j++)
#pragma unroll
                for (int r = 0; r < 4; r++) acc[i][j][r] = 0.0f;

#pragma unroll
        for (int s = 0; s < STAGES - 1; s++)
            gemm_load_tile(&sm[s], Ab, Wb, K, N, s * BK, tid);

        for (int kt = 0; kt < NT; kt++) {
            const int rem = NT - 1 - kt;
            if (rem >= STAGES - 2)      CP_WAITG(STAGES - 2);
            else                        CP_WAITG(0);
            __syncthreads();

            if (kt + STAGES - 1 < NT)
                gemm_load_tile(&sm[(kt + STAGES - 1) % STAGES], Ab, Wb, K, N,
                               (kt + STAGES - 1) * BK, tid);

            const SmemTile& S = sm[kt % STAGES];
            const uint32_t aBase = smem_u32(&S) + lmOff;
#pragma unroll
            for (int ks = 0; ks < 4; ks++) {
                const int kk = ks * 8;
                uint32_t af[4][4], bf[4][2];
#pragma unroll
                for (int mf = 0; mf < 4; mf++)
                    LDSM_X4(af[mf], aBase + (uint32_t)(mf * 16 * APAD * 4) + (uint32_t)(ks * 32));
#pragma unroll
                for (int nf = 0; nf < 4; nf++) {
                    const int cB = wn * 32 + nf * 8 + g;
                    bf[nf][0] = __float_as_uint(S.Bs[kk + t][cB]);
                    bf[nf][1] = __float_as_uint(S.Bs[kk + t + 4][cB]);
                }
#pragma unroll
                for (int mf = 0; mf < 4; mf++)
#pragma unroll
                    for (int nf = 0; nf < 4; nf++)
                        mma_tf32(acc[mf][nf], af[mf], bf[nf]);
            }
        }

        if (MODE == 0) {
#pragma unroll
            for (int mf = 0; mf < 4; mf++) {
                const int row = m0 + wm * 64 + mf * 16 + g;
#pragma unroll
                for (int nf = 0; nf < 4; nf++) {
                    const int col = n0 + wn * 32 + nf * 8 + 2 * t;
                    const float b0 = bias[col], b1 = bias[col + 1];
                    float2 v0 = { acc[mf][nf][0] + b0, acc[mf][nf][1] + b1 };
                    float2 v1 = { acc[mf][nf][2] + b0, acc[mf][nf][3] + b1 };
                    *(float2*)(C + (size_t)row * N + col) = v0;
                    *(float2*)(C + (size_t)(row + 8) * N + col) = v1;
                }
            }
        } else {
            const float qscale = 8.0f / (float)D_;
            const int seg = n0 >> 11;   // 0:Q 1:K 2:V
#pragma unroll
            for (int mf = 0; mf < 4; mf++) {
                const int row0 = m0 + wm * 64 + mf * 16 + g;
#pragma unroll
                for (int nf = 0; nf < 4; nf++) {
                    const int col = n0 + wn * 32 + nf * 8 + 2 * t;
                    const float b0 = bias[col], b1 = bias[col + 1];
                    float v0 = acc[mf][nf][0] + b0, v1 = acc[mf][nf][1] + b1;
                    float w0 = acc[mf][nf][2] + b0, w1 = acc[mf][nf][3] + b1;
                    if (seg == 2) {
                        float2* p0 = (float2*)(Vout + (size_t)row0 * E_ + (col - 2 * E_));
                        float2* p1 = (float2*)(Vout + (size_t)(row0 + 8) * E_ + (col - 2 * E_));
                        *p0 = make_float2(v0, v1);
                        *p1 = make_float2(w0, w1);
                    } else {
                        if (seg == 0) { v0 *= qscale; v1 *= qscale; w0 *= qscale; w1 *= qscale; }
                        const int cl = col & 2047;
                        const int h = cl >> 6, dp = (cl & 63) >> 1;
                        uint32_t* OH = (seg == 0) ? QHo : KHo;
                        uint32_t* OL = (seg == 0) ? QLo : KLo;
                        const int bb = row0 >> 11, tt = row0 & 2047;
                        const size_t oi = ((size_t)(bb * 32 + h) * T_ + tt) * 32 + dp;
                        uint32_t hi, lo;
                        split2f(v0, v1, hi, lo);
                        OH[oi] = hi; OL[oi] = lo;
                        split2f(w0, w1, hi, lo);
                        OH[oi + 8 * 32] = hi; OL[oi + 8 * 32] = lo;
                    }
                }
            }
        }
        __syncthreads();   // all smem reads done before next tile's prologue
    }
}

// ---------------------------------------------------------------------------
// Flash attention (round-14 structure; 128-row q-tile, 2-stage pipeline)
// ---------------------------------------------------------------------------
#define FST 36
#define FARR (64 * FST)
#define FARRB (FARR * 4)
#define FLASH_SMEM (2 * 4 * FARRB)

__device__ __forceinline__ void load_kv_tile(uint32_t sbase,
                                             const uint32_t* __restrict__ kh,
                                             const uint32_t* __restrict__ kl,
                                             const uint32_t* __restrict__ vh,
                                             const uint32_t* __restrict__ vl,
                                             int tid) {
#pragma unroll
    for (int i = 0; i < 2; i++) {
        int idx = tid + 256 * i, r = idx >> 3, c = (idx & 7) * 4;
        CP_ASYNC16(sbase + (uint32_t)(r * FST + c) * 4u, kh + (size_t)r * 32 + c);
    }
#pragma unroll
    for (int i = 0; i < 2; i++) {
        int idx = tid + 256 * i, r = idx >> 3, c = (idx & 7) * 4;
        CP_ASYNC16(sbase + FARRB + (uint32_t)(r * FST + c) * 4u, kl + (size_t)r * 32 + c);
    }
#pragma unroll
    for (int i = 0; i < 2; i++) {
        int idx = tid + 256 * i, r = idx >> 3, c = (idx & 7) * 4;
        CP_ASYNC16(sbase + 2 * FARRB + (uint32_t)(r * FST + c) * 4u, vh + (size_t)r * (T_ / 2) + c);
    }
#pragma unroll
    for (int i = 0; i < 2; i++) {
        int idx = tid + 256 * i, r = idx >> 3, c = (idx & 7) * 4;
        CP_ASYNC16(sbase + 3 * FARRB + (uint32_t)(r * FST + c) * 4u, vl + (size_t)r * (T_ / 2) + c);
    }
    CP_COMMIT();
}

__global__ __launch_bounds__(256, 1)
void flash_mma(const uint32_t* __restrict__ gQH, const uint32_t* __restrict__ gQL,
               const uint32_t* __restrict__ gKH, const uint32_t* __restrict__ gKL,
               const uint32_t* __restrict__ gVH, const uint32_t* __restrict__ gVL,
               float* __restrict__ out) {
    extern __shared__ uint32_t fsm[];
    const uint32_t sbase = smem_u32(fsm);

    const int tid = threadIdx.x;
    const int wid = tid >> 5, lane = tid & 31;
    const int g = lane >> 2, t = lane & 3;

    const int qb = blockIdx.x;
    const int bh = blockIdx.y;
    const int b = bh >> 5;
    const int h = bh & 31;

    const float slope = exp2f(-0.25f * (float)(h + 1));
    const int q0 = qb * 128;
    const int rW = wid * 16;
    const int qg0 = q0 + rW + g;
    const int qg1 = qg0 + 8;

    const uint32_t* bKH = gKH + (size_t)bh * T_ * 32;
    const uint32_t* bKL = gKL + (size_t)bh * T_ * 32;
    const uint32_t* bVH = gVH + (size_t)bh * 64 * (T_ / 2);
    const uint32_t* bVL = gVL + (size_t)bh * 64 * (T_ / 2);

    uint32_t qah[4][4], qal[4][4];
    {
        const uint32_t* q0p = gQH + ((size_t)bh * T_ + qg0) * 32;
        const uint32_t* q1p = gQH + ((size_t)bh * T_ + qg1) * 32;
        const uint32_t* q0l = gQL + ((size_t)bh * T_ + qg0) * 32;
        const uint32_t* q1l = gQL + ((size_t)bh * T_ + qg1) * 32;
#pragma unroll
        for (int kt = 0; kt < 4; kt++) {
            qah[kt][0] = q0p[kt * 8 + t];
            qah[kt][1] = q1p[kt * 8 + t];
            qah[kt][2] = q0p[kt * 8 + t + 4];
            qah[kt][3] = q1p[kt * 8 + t + 4];
            qal[kt][0] = q0l[kt * 8 + t];
            qal[kt][1] = q1l[kt * 8 + t];
            qal[kt][2] = q0l[kt * 8 + t + 4];
            qal[kt][3] = q1l[kt * 8 + t + 4];
        }
    }

    float o[8][4];
#pragma unroll
    for (int nf = 0; nf < 8; nf++)
#pragma unroll
        for (int r = 0; r < 4; r++) o[nf][r] = 0.0f;
    float m0 = -1e30f, m1 = -1e30f, l0 = 0.0f, l1 = 0.0f;

    const int nkb = 2 * qb + 2;

    load_kv_tile(sbase, bKH, bKL, bVH, bVL, tid);

    for (int kb = 0; kb < nkb; kb++) {
        CP_WAITG(0);
        __syncthreads();
        if (kb + 1 < nkb)
            load_kv_tile(sbase + ((kb + 1) & 1) * 4 * FARRB,
                         bKH + (size_t)(kb + 1) * 64 * 32,
                         bKL + (size_t)(kb + 1) * 64 * 32,
                         bVH + (size_t)(kb + 1) * 32,
                         bVL + (size_t)(kb + 1) * 32, tid);

        if (wid < 4 && kb == 2 * qb + 1) continue;

        const uint32_t* sKH = fsm + (kb & 1) * 4 * FARR;
        const uint32_t* sKL = sKH + FARR;
        const uint32_t* sVH = sKH + 2 * FARR;
        const uint32_t* sVL = sKH + 3 * FARR;

        float c[8][4];
#pragma unroll
        for (int nf = 0; nf < 8; nf++)
#pragma unroll
            for (int r = 0; r < 4; r++) c[nf][r] = 0.0f;

#pragma unroll
        for (int kt = 0; kt < 4; kt++) {
#pragma unroll
            for (int nf = 0; nf < 8; nf++) {
                const int rB = (8 * nf + g) * FST + kt * 8 + t;
                uint32_t bh0 = sKH[rB], bh1 = sKH[rB + 4];
                uint32_t bl0 = sKL[rB], bl1 = sKL[rB + 4];
                mma_bf16(c[nf], qah[kt], bh0, bh1);
                mma_bf16(c[nf], qal[kt], bh0, bh1);
                mma_bf16(c[nf], qah[kt], bl0, bl1);
            }
        }

        if (kb >= 2 * qb) {
#pragma unroll
            for (int nf = 0; nf < 8; nf++) {
                const int col0 = kb * 64 + 8 * nf + 2 * t;
                const int col1 = col0 + 1;
                c[nf][0] = (col0 > qg0) ? -1e30f : c[nf][0] + slope * (float)(col0 - qg0);
                c[nf][1] = (col1 > qg0) ? -1e30f : c[nf][1] + slope * (float)(col1 - qg0);
                c[nf][2] = (col0 > qg1) ? -1e30f : c[nf][2] + slope * (float)(col0 - qg1);
                c[nf][3] = (col1 > qg1) ? -1e30f : c[nf][3] + slope * (float)(col1 - qg1);
            }
        } else {
#pragma unroll
            for (int nf = 0; nf < 8; nf++) {
                const int col0 = kb * 64 + 8 * nf + 2 * t;
                const int col1 = col0 + 1;
                c[nf][0] += slope * (float)(col0 - qg0);
                c[nf][1] += slope * (float)(col1 - qg0);
                c[nf][2] += slope * (float)(col0 - qg1);
                c[nf][3] += slope * (float)(col1 - qg1);
            }
        }

        float mx0 = -1e30f, mx1 = -1e30f;
#pragma unroll
        for (int nf = 0; nf < 8; nf++) {
            mx0 = fmaxf(mx0, fmaxf(c[nf][0], c[nf][1]));
            mx1 = fmaxf(mx1, fmaxf(c[nf][2], c[nf][3]));
        }
        mx0 = fmaxf(mx0, __shfl_xor_sync(0xffffffffu, mx0, 1));
        mx0 = fmaxf(mx0, __shfl_xor_sync(0xffffffffu, mx0, 2));
        mx1 = fmaxf(mx1, __shfl_xor_sync(0xffffffffu, mx1, 1));
        mx1 = fmaxf(mx1, __shfl_xor_sync(0xffffffffu, mx1, 2));

        const float mn0 = fmaxf(m0, mx0), mn1 = fmaxf(m1, mx1);
        const float alpha0 = __expf(m0 - mn0), alpha1 = __expf(m1 - mn1);
        m0 = mn0; m1 = mn1;

        float s0 = 0.0f, s1 = 0.0f;
#pragma unroll
        for (int nf = 0; nf < 8; nf++) {
            c[nf][0] = __expf(c[nf][0] - m0);
            c[nf][1] = __expf(c[nf][1] - m0);
            c[nf][2] = __expf(c[nf][2] - m1);
            c[nf][3] = __expf(c[nf][3] - m1);
            s0 += c[nf][0] + c[nf][1];
            s1 += c[nf][2] + c[nf][3];
        }
        s0 += __shfl_xor_sync(0xffffffffu, s0, 1);
        s0 += __shfl_xor_sync(0xffffffffu, s0, 2);
        s1 += __shfl_xor_sync(0xffffffffu, s1, 1);
        s1 += __shfl_xor_sync(0xffffffffu, s1, 2);
        l0 = l0 * alpha0 + s0;
        l1 = l1 * alpha1 + s1;

        uint32_t pah[4][4], pal[4][4];
#pragma unroll
        for (int kt = 0; kt < 4; kt++) {
            split2f(c[2 * kt][0],     c[2 * kt][1],     pah[kt][0], pal[kt][0]);
            split2f(c[2 * kt][2],     c[2 * kt][3],     pah[kt][1], pal[kt][1]);
            split2f(c[2 * kt + 1][0], c[2 * kt + 1][1], pah[kt][2], pal[kt][2]);
            split2f(c[2 * kt + 1][2], c[2 * kt + 1][3], pah[kt][3], pal[kt][3]);
        }

#pragma unroll
        for (int nf = 0; nf < 8; nf++) {
            o[nf][0] *= alpha0; o[nf][1] *= alpha0;
            o[nf][2] *= alpha1; o[nf][3] *= alpha1;
        }

#pragma unroll
        for (int kt = 0; kt < 4; kt++) {
#pragma unroll
            for (int nf = 0; nf < 8; nf++) {
                const int rB = (8 * nf + g) * FST + kt * 8 + t;
                uint32_t bh0 = sVH[rB], bh1 = sVH[rB + 4];
                uint32_t bl0 = sVL[rB], bl1 = sVL[rB + 4];
                mma_bf16(o[nf], pah[kt], bh0, bh1);
                mma_bf16(o[nf], pal[kt], bh0, bh1);
                mma_bf16(o[nf], pah[kt], bl0, bl1);
            }
        }
    }

    const float inv0 = 1.0f / l0, inv1 = 1.0f / l1;
    float* o0 = out + ((size_t)b * T_ + qg0) * E_ + h * D_;
    float* o1 = out + ((size_t)b * T_ + qg1) * E_ + h * D_;
#pragma unroll
    for (int nf = 0; nf < 8; nf++) {
        const int col = 8 * nf + 2 * t;
        float2 v0 = { __uint_as_float(f2tf32(o[nf][0] * inv0)),
                      __uint_as_float(f2tf32(o[nf][1] * inv0)) };
        float2 v1 = { __uint_as_float(f2tf32(o[nf][2] * inv1)),
                      __uint_as_float(f2tf32(o[nf][3] * inv1)) };
        *(float2*)(o0 + col) = v0;
        *(float2*)(o1 + col) = v1;
    }
}

// ---------------------------------------------------------------------------
extern "C" void kernel_launch(void* const* d_in, const int* in_sizes, int n_in,
                              void* d_out, int out_size) {
    const float* x    = (const float*)d_in[0];
    const float* Wqkv = (const float*)d_in[1];
    const float* bqkv = (const float*)d_in[2];
    const float* Wout = (const float*)d_in[3];
    const float* bout = (const float*)d_in[4];
    float* out = (float*)d_out;

    float *vbuf, *att, *rx, *rwq, *rwo;
    uint32_t *pQH, *pQL, *pKH, *pKL, *pVH, *pVL;
    cudaGetSymbolAddress((void**)&vbuf, g_vbuf);
    cudaGetSymbolAddress((void**)&att,  g_att);
    cudaGetSymbolAddress((void**)&rx,   g_rx);
    cudaGetSymbolAddress((void**)&rwq,  g_rwq);
    cudaGetSymbolAddress((void**)&rwo,  g_rwo);
    cudaGetSymbolAddress((void**)&pQH,  g_QH);
    cudaGetSymbolAddress((void**)&pQL,  g_QL);
    cudaGetSymbolAddress((void**)&pKH,  g_KH);
    cudaGetSymbolAddress((void**)&pKL,  g_KL);
    cudaGetSymbolAddress((void**)&pVH,  g_VH);
    cudaGetSymbolAddress((void**)&pVL,  g_VL);

    cudaFuncSetAttribute(flash_mma, cudaFuncAttributeMaxDynamicSharedMemorySize, FLASH_SMEM);
    cudaFuncSetAttribute(mma_gemm<0>, cudaFuncAttributeMaxDynamicSharedMemorySize, GEMM_SMEM);
    cudaFuncSetAttribute(mma_gemm<1>, cudaFuncAttributeMaxDynamicSharedMemorySize, GEMM_SMEM);

    // 0) pre-round inputs/weights to tf32 bit patterns
    {
        int n4;
        n4 = (B_ * T_ * E_) / 4;
        round_tf32<<<(n4 + 255) / 256, 256>>>((const float4*)x, (float4*)rx, n4);
        n4 = (E_ * THREE_E) / 4;
        round_tf32<<<(n4 + 255) / 256, 256>>>((const float4*)Wqkv, (float4*)rwq, n4);
        n4 = (E_ * E_) / 4;
        round_tf32<<<(n4 + 255) / 256, 256>>>((const float4*)Wout, (float4*)rwo, n4);
    }

    // 1) QKV projection (persistent tiles) with fused Q/K split + V dense store
    {
        int tiles = (THREE_E / BN) * ((B_ * T_) / BM);
        int grid = tiles < PERSIST_CTAS ? tiles : PERSIST_CTAS;
        mma_gemm<1><<<grid, NTHR, GEMM_SMEM>>>(
            B_ * T_, THREE_E, E_, rx, rwq, bqkv, nullptr,
            pQH, pQL, pKH, pKL, vbuf);
    }

    // 1b) V transpose+split only
    prep_v<<<dim3(T_ / 64, B_ * H_), 128>>>(vbuf, pVH, pVL);

    // 2) Flash attention (128-row q-tiles)
    flash_mma<<<dim3(T_ / 128, B_ * H_), 256, FLASH_SMEM>>>(
        pQH, pQL, pKH, pKL, pVH, pVL, att);

    // 3) Output projection (persistent tiles, plain epilogue)
    {
        int tiles = (E_ / BN) * ((B_ * T_) / BM);
        int grid = tiles < PERSIST_CTAS ? tiles : PERSIST_CTAS;
        mma_gemm<0><<<grid, NTHR, GEMM_SMEM>>>(
            B_ * T_, E_, E_, att, rwo, bout, out,
            nullptr, nullptr, nullptr, nullptr, nullptr);
    }
}

// round 17
// speedup vs baseline: 1.0549x; 1.0549x over previous
#include <cuda_runtime.h>
#include <cuda_bf16.h>
#include <cstdint>

#define B_ 2
#define T_ 2048
#define E_ 2048
#define H_ 32
#define D_ 64
#define THREE_E (3 * E_)

// Scratch (no allocs allowed anywhere).
__device__ float g_vbuf[(size_t)B_ * T_ * E_];
__device__ float g_att[(size_t)B_ * T_ * E_];
__device__ float g_rx[(size_t)B_ * T_ * E_];
__device__ float g_rwq[(size_t)E_ * THREE_E];
__device__ float g_rwo[(size_t)E_ * E_];
#define SPLN ((size_t)B_ * H_ * T_ * 32)
__device__ uint32_t g_QH[SPLN], g_QL[SPLN];
__device__ uint32_t g_KH[SPLN], g_KL[SPLN];
__device__ uint32_t g_VH[SPLN], g_VL[SPLN];

// ---------------------------------------------------------------------------
// helpers
// ---------------------------------------------------------------------------
__device__ __forceinline__ uint32_t smem_u32(const void* p) {
    uint32_t a;
    asm("{ .reg .u64 t; cvta.to.shared.u64 t, %1; cvt.u32.u64 %0, t; }" : "=r"(a) : "l"(p));
    return a;
}
#define CP_ASYNC16(dst, src) \
    asm volatile("cp.async.cg.shared.global [%0], [%1], 16;" :: "r"(dst), "l"(src))
#define CP_COMMIT() asm volatile("cp.async.commit_group;" ::: "memory")
#define CP_WAITG(n) asm volatile("cp.async.wait_group %0;" :: "n"(n) : "memory")

#define LDSM_X4(r, a)                                                            \
    asm volatile("ldmatrix.sync.aligned.m8n8.x4.shared.b16 {%0,%1,%2,%3}, [%4];" \
        : "=r"((r)[0]), "=r"((r)[1]), "=r"((r)[2]), "=r"((r)[3]) : "r"(a))

__device__ __forceinline__ uint32_t f2tf32(float x) {
    uint32_t r;
    asm("cvt.rna.tf32.f32 %0, %1;" : "=r"(r) : "f"(x));
    return r;
}

__device__ __forceinline__ void mma_tf32(float* c, const uint32_t* a, const uint32_t* b) {
    asm volatile(
        "mma.sync.aligned.m16n8k8.row.col.f32.tf32.tf32.f32 "
        "{%0,%1,%2,%3}, {%4,%5,%6,%7}, {%8,%9}, {%0,%1,%2,%3};"
        : "+f"(c[0]), "+f"(c[1]), "+f"(c[2]), "+f"(c[3])
        : "r"(a[0]), "r"(a[1]), "r"(a[2]), "r"(a[3]), "r"(b[0]), "r"(b[1]));
}

__device__ __forceinline__ void mma_bf16(float* c, const uint32_t* a, uint32_t b0, uint32_t b1) {
    asm volatile(
        "mma.sync.aligned.m16n8k16.row.col.f32.bf16.bf16.f32 "
        "{%0,%1,%2,%3}, {%4,%5,%6,%7}, {%8,%9}, {%0,%1,%2,%3};"
        : "+f"(c[0]), "+f"(c[1]), "+f"(c[2]), "+f"(c[3])
        : "r"(a[0]), "r"(a[1]), "r"(a[2]), "r"(a[3]), "r"(b0), "r"(b1));
}

__device__ __forceinline__ void split2f(float x, float y, uint32_t& hi, uint32_t& lo) {
    uint32_t h;
    asm("cvt.rn.bf16x2.f32 %0, %1, %2;" : "=r"(h) : "f"(y), "f"(x));
    float hx, hy;
    asm("{ .reg .b16 a, b;\n\t"
        "mov.b32 {a, b}, %2;\n\t"
        "cvt.f32.bf16 %0, a;\n\t"
        "cvt.f32.bf16 %1, b;\n\t}"
        : "=f"(hx), "=f"(hy) : "r"(h));
    uint32_t l;
    float rx = x - hx, ry = y - hy;
    asm("cvt.rn.bf16x2.f32 %0, %1, %2;" : "=r"(l) : "f"(ry), "f"(rx));
    hi = h; lo = l;
}

// ---------------------------------------------------------------------------
// Single fused pre-round pass: x, Wqkv, Wout -> tf32 bit patterns
// ---------------------------------------------------------------------------
__global__ void round_all(const float4* __restrict__ i0, float4* __restrict__ o0, int n0,
                          const float4* __restrict__ i1, float4* __restrict__ o1, int n1,
                          const float4* __restrict__ i2, float4* __restrict__ o2, int n2) {
    int i = blockIdx.x * blockDim.x + threadIdx.x;
    const float4* in;
    float4* out;
    if (i < n0)            { in = i0 + i; out = o0 + i; }
    else if (i < n0 + n1)  { in = i1 + (i - n0); out = o1 + (i - n0); }
    else if (i < n0 + n1 + n2) { in = i2 + (i - n0 - n1); out = o2 + (i - n0 - n1); }
    else return;
    float4 v = *in;
    float4 r;
    r.x = __uint_as_float(f2tf32(v.x));
    r.y = __uint_as_float(f2tf32(v.y));
    r.z = __uint_as_float(f2tf32(v.z));
    r.w = __uint_as_float(f2tf32(v.w));
    *out = r;
}

// ---------------------------------------------------------------------------
// prep_v: V dense [B*T][E] -> transposed split arrays [bh][d][T/2].
// Smem-staged: coalesced reads (d fast) AND coalesced writes (kp fast).
// Bit-identical values to the direct version.
// ---------------------------------------------------------------------------
__global__ __launch_bounds__(256)
void prep_v(const float* __restrict__ V,
            uint32_t* __restrict__ VH, uint32_t* __restrict__ VL) {
    __shared__ float s[64][65];
    const int tid = threadIdx.x;
    const int tb = blockIdx.x, bh = blockIdx.y;
    const int b = bh >> 5, h = bh & 31;
    const float* basep = V + (size_t)b * T_ * E_ + (size_t)(tb * 64) * E_ + h * 64;
#pragma unroll
    for (int i = 0; i < 16; i++) {
        int idx = tid + 256 * i;
        int t = idx >> 6, d = idx & 63;
        s[t][d] = basep[(size_t)t * E_ + d];
    }
    __syncthreads();
#pragma unroll
    for (int i = 0; i < 8; i++) {
        int idx = tid + 256 * i;
        int d = idx >> 5, kp = idx & 31;
        uint32_t hi, lo;
        split2f(s[2 * kp][d], s[2 * kp + 1][d], hi, lo);
        const size_t oi = ((size_t)bh * 64 + d) * (T_ / 2) + tb * 32 + kp;
        VH[oi] = hi; VL[oi] = lo;
    }
}

// ---------------------------------------------------------------------------
// tf32 tensor-core GEMM (round-13/15 proven, NON-persistent): BK=32, 3 stages.
// MODE 0: plain store.  MODE 1: fused QKV epilogue.
// ---------------------------------------------------------------------------
#define BM 128
#define BN 128
#define BK 32
#define APAD 36
#define BPAD 136
#define NTHR 256
#define STAGES 3

struct SmemTile {
    float As[BM][APAD];
    float Bs[BK][BPAD];
};
#define GEMM_SMEM (STAGES * (int)sizeof(SmemTile))

__device__ __forceinline__ void gemm_load_tile(SmemTile* st,
                                               const float* __restrict__ Ab,
                                               const float* __restrict__ Wb,
                                               int K, int N, int k0, int tid) {
#pragma unroll
    for (int it = 0; it < 4; it++) {
        int idx = tid + NTHR * it;
        int m = idx >> 3, kc = idx & 7;
        CP_ASYNC16(smem_u32(&st->As[m][kc * 4]), Ab + (size_t)m * K + k0 + kc * 4);
    }
#pragma unroll
    for (int it = 0; it < 4; it++) {
        int idx = tid + NTHR * it;
        int k = idx >> 5, c = idx & 31;
        CP_ASYNC16(smem_u32(&st->Bs[k][c * 4]), Wb + (size_t)(k0 + k) * N + c * 4);
    }
    CP_COMMIT();
}

template <int MODE>
__global__ __launch_bounds__(NTHR, 2)
void mma_gemm(int M, int N, int K,
              const float* __restrict__ A,
              const float* __restrict__ W,
              const float* __restrict__ bias,
              float* __restrict__ C,
              uint32_t* __restrict__ QHo, uint32_t* __restrict__ QLo,
              uint32_t* __restrict__ KHo, uint32_t* __restrict__ KLo,
              float* __restrict__ Vout) {
    extern __shared__ SmemTile sm[];

    const int tid = threadIdx.x;
    const int wid = tid >> 5, lane = tid & 31;
    const int wm = wid >> 2, wn = wid & 3;
    const int g = lane >> 2, t = lane & 3;

    const int m0 = blockIdx.y * BM;
    const int n0 = blockIdx.x * BN;

    const float* Ab = A + (size_t)m0 * K;
    const float* Wb = W + n0;

    const uint32_t lmOff = ((uint32_t)(wm * 64 + (lane & 15)) * APAD) * 4u
                         + ((uint32_t)(lane >> 4)) * 16u;

    float acc[4][4][4];
#pragma unroll
    for (int i = 0; i < 4; i++)
#pragma unroll
        for (int j = 0; j < 4; j++)
#pragma unroll
            for (int r = 0; r < 4; r++) acc[i][j][r] = 0.0f;

    const int NT = K / BK;

#pragma unroll
    for (int s = 0; s < STAGES - 1; s++)
        gemm_load_tile(&sm[s], Ab, Wb, K, N, s * BK, tid);

    for (int kt = 0; kt < NT; kt++) {
        const int rem = NT - 1 - kt;
        if (rem >= STAGES - 2)      CP_WAITG(STAGES - 2);
        else                        CP_WAITG(0);
        __syncthreads();

        if (kt + STAGES - 1 < NT)
            gemm_load_tile(&sm[(kt + STAGES - 1) % STAGES], Ab, Wb, K, N,
                           (kt + STAGES - 1) * BK, tid);

        const SmemTile& S = sm[kt % STAGES];
        const uint32_t aBase = smem_u32(&S) + lmOff;
#pragma unroll
        for (int ks = 0; ks < 4; ks++) {
            const int kk = ks * 8;
            uint32_t af[4][4], bf[4][2];
#pragma unroll
            for (int mf = 0; mf < 4; mf++)
                LDSM_X4(af[mf], aBase + (uint32_t)(mf * 16 * APAD * 4) + (uint32_t)(ks * 32));
#pragma unroll
            for (int nf = 0; nf < 4; nf++) {
                const int cB = wn * 32 + nf * 8 + g;
                bf[nf][0] = __float_as_uint(S.Bs[kk + t][cB]);
                bf[nf][1] = __float_as_uint(S.Bs[kk + t + 4][cB]);
            }
#pragma unroll
            for (int mf = 0; mf < 4; mf++)
#pragma unroll
                for (int nf = 0; nf < 4; nf++)
                    mma_tf32(acc[mf][nf], af[mf], bf[nf]);
        }
    }

    if (MODE == 0) {
#pragma unroll
        for (int mf = 0; mf < 4; mf++) {
            const int row = m0 + wm * 64 + mf * 16 + g;
#pragma unroll
            for (int nf = 0; nf < 4; nf++) {
                const int col = n0 + wn * 32 + nf * 8 + 2 * t;
                const float b0 = bias[col], b1 = bias[col + 1];
                float2 v0 = { acc[mf][nf][0] + b0, acc[mf][nf][1] + b1 };
                float2 v1 = { acc[mf][nf][2] + b0, acc[mf][nf][3] + b1 };
                *(float2*)(C + (size_t)row * N + col) = v0;
                *(float2*)(C + (size_t)(row + 8) * N + col) = v1;
            }
        }
    } else {
        const float qscale = 8.0f / (float)D_;
        const int seg = n0 >> 11;   // 0:Q 1:K 2:V
#pragma unroll
        for (int mf = 0; mf < 4; mf++) {
            const int row0 = m0 + wm * 64 + mf * 16 + g;
#pragma unroll
            for (int nf = 0; nf < 4; nf++) {
                const int col = n0 + wn * 32 + nf * 8 + 2 * t;
                const float b0 = bias[col], b1 = bias[col + 1];
                float v0 = acc[mf][nf][0] + b0, v1 = acc[mf][nf][1] + b1;
                float w0 = acc[mf][nf][2] + b0, w1 = acc[mf][nf][3] + b1;
                if (seg == 2) {
                    float2* p0 = (float2*)(Vout + (size_t)row0 * E_ + (col - 2 * E_));
                    float2* p1 = (float2*)(Vout + (size_t)(row0 + 8) * E_ + (col - 2 * E_));
                    *p0 = make_float2(v0, v1);
                    *p1 = make_float2(w0, w1);
                } else {
                    if (seg == 0) { v0 *= qscale; v1 *= qscale; w0 *= qscale; w1 *= qscale; }
                    const int cl = col & 2047;
                    const int h = cl >> 6, dp = (cl & 63) >> 1;
                    uint32_t* OH = (seg == 0) ? QHo : KHo;
                    uint32_t* OL = (seg == 0) ? QLo : KLo;
                    const int bb = row0 >> 11, tt = row0 & 2047;
                    const size_t oi = ((size_t)(bb * 32 + h) * T_ + tt) * 32 + dp;
                    uint32_t hi, lo;
                    split2f(v0, v1, hi, lo);
                    OH[oi] = hi; OL[oi] = lo;
                    split2f(w0, w1, hi, lo);
                    OH[oi + 8 * 32] = hi; OL[oi + 8 * 32] = lo;
                }
            }
        }
    }
}

// ---------------------------------------------------------------------------
// Flash attention (round-14/15 proven): 128-row q-tile, 256 threads,
// 2-stage cp.async pipeline, diagonal-only masking, full-mask warp skip.
// ---------------------------------------------------------------------------
#define FST 36
#define FARR (64 * FST)
#define FARRB (FARR * 4)
#define FLASH_SMEM (2 * 4 * FARRB)

__device__ __forceinline__ void load_kv_tile(uint32_t sbase,
                                             const uint32_t* __restrict__ kh,
                                             const uint32_t* __restrict__ kl,
                                             const uint32_t* __restrict__ vh,
                                             const uint32_t* __restrict__ vl,
                                             int tid) {
#pragma unroll
    for (int i = 0; i < 2; i++) {
        int idx = tid + 256 * i, r = idx >> 3, c = (idx & 7) * 4;
        CP_ASYNC16(sbase + (uint32_t)(r * FST + c) * 4u, kh + (size_t)r * 32 + c);
    }
#pragma unroll
    for (int i = 0; i < 2; i++) {
        int idx = tid + 256 * i, r = idx >> 3, c = (idx & 7) * 4;
        CP_ASYNC16(sbase + FARRB + (uint32_t)(r * FST + c) * 4u, kl + (size_t)r * 32 + c);
    }
#pragma unroll
    for (int i = 0; i < 2; i++) {
        int idx = tid + 256 * i, r = idx >> 3, c = (idx & 7) * 4;
        CP_ASYNC16(sbase + 2 * FARRB + (uint32_t)(r * FST + c) * 4u, vh + (size_t)r * (T_ / 2) + c);
    }
#pragma unroll
    for (int i = 0; i < 2; i++) {
        int idx = tid + 256 * i, r = idx >> 3, c = (idx & 7) * 4;
        CP_ASYNC16(sbase + 3 * FARRB + (uint32_t)(r * FST + c) * 4u, vl + (size_t)r * (T_ / 2) + c);
    }
    CP_COMMIT();
}

__global__ __launch_bounds__(256, 1)
void flash_mma(const uint32_t* __restrict__ gQH, const uint32_t* __restrict__ gQL,
               const uint32_t* __restrict__ gKH, const uint32_t* __restrict__ gKL,
               const uint32_t* __restrict__ gVH, const uint32_t* __restrict__ gVL,
               float* __restrict__ out) {
    extern __shared__ uint32_t fsm[];
    const uint32_t sbase = smem_u32(fsm);

    const int tid = threadIdx.x;
    const int wid = tid >> 5, lane = tid & 31;
    const int g = lane >> 2, t = lane & 3;

    const int qb = blockIdx.x;
    const int bh = blockIdx.y;
    const int b = bh >> 5;
    const int h = bh & 31;

    const float slope = exp2f(-0.25f * (float)(h + 1));
    const int q0 = qb * 128;
    const int rW = wid * 16;
    const int qg0 = q0 + rW + g;
    const int qg1 = qg0 + 8;

    const uint32_t* bKH = gKH + (size_t)bh * T_ * 32;
    const uint32_t* bKL = gKL + (size_t)bh * T_ * 32;
    const uint32_t* bVH = gVH + (size_t)bh * 64 * (T_ / 2);
    const uint32_t* bVL = gVL + (size_t)bh * 64 * (T_ / 2);

    uint32_t qah[4][4], qal[4][4];
    {
        const uint32_t* q0p = gQH + ((size_t)bh * T_ + qg0) * 32;
        const uint32_t* q1p = gQH + ((size_t)bh * T_ + qg1) * 32;
        const uint32_t* q0l = gQL + ((size_t)bh * T_ + qg0) * 32;
        const uint32_t* q1l = gQL + ((size_t)bh * T_ + qg1) * 32;
#pragma unroll
        for (int kt = 0; kt < 4; kt++) {
            qah[kt][0] = q0p[kt * 8 + t];
            qah[kt][1] = q1p[kt * 8 + t];
            qah[kt][2] = q0p[kt * 8 + t + 4];
            qah[kt][3] = q1p[kt * 8 + t + 4];
            qal[kt][0] = q0l[kt * 8 + t];
            qal[kt][1] = q1l[kt * 8 + t];
            qal[kt][2] = q0l[kt * 8 + t + 4];
            qal[kt][3] = q1l[kt * 8 + t + 4];
        }
    }

    float o[8][4];
#pragma unroll
    for (int nf = 0; nf < 8; nf++)
#pragma unroll
        for (int r = 0; r < 4; r++) o[nf][r] = 0.0f;
    float m0 = -1e30f, m1 = -1e30f, l0 = 0.0f, l1 = 0.0f;

    const int nkb = 2 * qb + 2;

    load_kv_tile(sbase, bKH, bKL, bVH, bVL, tid);

    for (int kb = 0; kb < nkb; kb++) {
        CP_WAITG(0);
        __syncthreads();
        if (kb + 1 < nkb)
            load_kv_tile(sbase + ((kb + 1) & 1) * 4 * FARRB,
                         bKH + (size_t)(kb + 1) * 64 * 32,
                         bKL + (size_t)(kb + 1) * 64 * 32,
                         bVH + (size_t)(kb + 1) * 32,
                         bVL + (size_t)(kb + 1) * 32, tid);

        if (wid < 4 && kb == 2 * qb + 1) continue;

        const uint32_t* sKH = fsm + (kb & 1) * 4 * FARR;
        const uint32_t* sKL = sKH + FARR;
        const uint32_t* sVH = sKH + 2 * FARR;
        const uint32_t* sVL = sKH + 3 * FARR;

        float c[8][4];
#pragma unroll
        for (int nf = 0; nf < 8; nf++)
#pragma unroll
            for (int r = 0; r < 4; r++) c[nf][r] = 0.0f;

#pragma unroll
        for (int kt = 0; kt < 4; kt++) {
#pragma unroll
            for (int nf = 0; nf < 8; nf++) {
                const int rB = (8 * nf + g) * FST + kt * 8 + t;
                uint32_t bh0 = sKH[rB], bh1 = sKH[rB + 4];
                uint32_t bl0 = sKL[rB], bl1 = sKL[rB + 4];
                mma_bf16(c[nf], qah[kt], bh0, bh1);
                mma_bf16(c[nf], qal[kt], bh0, bh1);
                mma_bf16(c[nf], qah[kt], bl0, bl1);
            }
        }

        if (kb >= 2 * qb) {
#pragma unroll
            for (int nf = 0; nf < 8; nf++) {
                const int col0 = kb * 64 + 8 * nf + 2 * t;
                const int col1 = col0 + 1;
                c[nf][0] = (col0 > qg0) ? -1e30f : c[nf][0] + slope * (float)(col0 - qg0);
                c[nf][1] = (col1 > qg0) ? -1e30f : c[nf][1] + slope * (float)(col1 - qg0);
                c[nf][2] = (col0 > qg1) ? -1e30f : c[nf][2] + slope * (float)(col0 - qg1);
                c[nf][3] = (col1 > qg1) ? -1e30f : c[nf][3] + slope * (float)(col1 - qg1);
            }
        } else {
#pragma unroll
            for (int nf = 0; nf < 8; nf++) {
                const int col0 = kb * 64 + 8 * nf + 2 * t;
                const int col1 = col0 + 1;
                c[nf][0] += slope * (float)(col0 - qg0);
                c[nf][1] += slope * (float)(col1 - qg0);
                c[nf][2] += slope * (float)(col0 - qg1);
                c[nf][3] += slope * (float)(col1 - qg1);
            }
        }

        float mx0 = -1e30f, mx1 = -1e30f;
#pragma unroll
        for (int nf = 0; nf < 8; nf++) {
            mx0 = fmaxf(mx0, fmaxf(c[nf][0], c[nf][1]));
            mx1 = fmaxf(mx1, fmaxf(c[nf][2], c[nf][3]));
        }
        mx0 = fmaxf(mx0, __shfl_xor_sync(0xffffffffu, mx0, 1));
        mx0 = fmaxf(mx0, __shfl_xor_sync(0xffffffffu, mx0, 2));
        mx1 = fmaxf(mx1, __shfl_xor_sync(0xffffffffu, mx1, 1));
        mx1 = fmaxf(mx1, __shfl_xor_sync(0xffffffffu, mx1, 2));

        const float mn0 = fmaxf(m0, mx0), mn1 = fmaxf(m1, mx1);
        const float alpha0 = __expf(m0 - mn0), alpha1 = __expf(m1 - mn1);
        m0 = mn0; m1 = mn1;

        float s0 = 0.0f, s1 = 0.0f;
#pragma unroll
        for (int nf = 0; nf < 8; nf++) {
            c[nf][0] = __expf(c[nf][0] - m0);
            c[nf][1] = __expf(c[nf][1] - m0);
            c[nf][2] = __expf(c[nf][2] - m1);
            c[nf][3] = __expf(c[nf][3] - m1);
            s0 += c[nf][0] + c[nf][1];
            s1 += c[nf][2] + c[nf][3];
        }
        s0 += __shfl_xor_sync(0xffffffffu, s0, 1);
        s0 += __shfl_xor_sync(0xffffffffu, s0, 2);
        s1 += __shfl_xor_sync(0xffffffffu, s1, 1);
        s1 += __shfl_xor_sync(0xffffffffu, s1, 2);
        l0 = l0 * alpha0 + s0;
        l1 = l1 * alpha1 + s1;

        uint32_t pah[4][4], pal[4][4];
#pragma unroll
        for (int kt = 0; kt < 4; kt++) {
            split2f(c[2 * kt][0],     c[2 * kt][1],     pah[kt][0], pal[kt][0]);
            split2f(c[2 * kt][2],     c[2 * kt][3],     pah[kt][1], pal[kt][1]);
            split2f(c[2 * kt + 1][0], c[2 * kt + 1][1], pah[kt][2], pal[kt][2]);
            split2f(c[2 * kt + 1][2], c[2 * kt + 1][3], pah[kt][3], pal[kt][3]);
        }

#pragma unroll
        for (int nf = 0; nf < 8; nf++) {
            o[nf][0] *= alpha0; o[nf][1] *= alpha0;
            o[nf][2] *= alpha1; o[nf][3] *= alpha1;
        }

#pragma unroll
        for (int kt = 0; kt < 4; kt++) {
#pragma unroll
            for (int nf = 0; nf < 8; nf++) {
                const int rB = (8 * nf + g) * FST + kt * 8 + t;
                uint32_t bh0 = sVH[rB], bh1 = sVH[rB + 4];
                uint32_t bl0 = sVL[rB], bl1 = sVL[rB + 4];
                mma_bf16(o[nf], pah[kt], bh0, bh1);
                mma_bf16(o[nf], pal[kt], bh0, bh1);
                mma_bf16(o[nf], pah[kt], bl0, bl1);
            }
        }
    }

    const float inv0 = 1.0f / l0, inv1 = 1.0f / l1;
    float* o0 = out + ((size_t)b * T_ + qg0) * E_ + h * D_;
    float* o1 = out + ((size_t)b * T_ + qg1) * E_ + h * D_;
#pragma unroll
    for (int nf = 0; nf < 8; nf++) {
        const int col = 8 * nf + 2 * t;
        float2 v0 = { __uint_as_float(f2tf32(o[nf][0] * inv0)),
                      __uint_as_float(f2tf32(o[nf][1] * inv0)) };
        float2 v1 = { __uint_as_float(f2tf32(o[nf][2] * inv1)),
                      __uint_as_float(f2tf32(o[nf][3] * inv1)) };
        *(float2*)(o0 + col) = v0;
        *(float2*)(o1 + col) = v1;
    }
}

// ---------------------------------------------------------------------------
extern "C" void kernel_launch(void* const* d_in, const int* in_sizes, int n_in,
                              void* d_out, int out_size) {
    const float* x    = (const float*)d_in[0];
    const float* Wqkv = (const float*)d_in[1];
    const float* bqkv = (const float*)d_in[2];
    const float* Wout = (const float*)d_in[3];
    const float* bout = (const float*)d_in[4];
    float* out = (float*)d_out;

    float *vbuf, *att, *rx, *rwq, *rwo;
    uint32_t *pQH, *pQL, *pKH, *pKL, *pVH, *pVL;
    cudaGetSymbolAddress((void**)&vbuf, g_vbuf);
    cudaGetSymbolAddress((void**)&att,  g_att);
    cudaGetSymbolAddress((void**)&rx,   g_rx);
    cudaGetSymbolAddress((void**)&rwq,  g_rwq);
    cudaGetSymbolAddress((void**)&rwo,  g_rwo);
    cudaGetSymbolAddress((void**)&pQH,  g_QH);
    cudaGetSymbolAddress((void**)&pQL,  g_QL);
    cudaGetSymbolAddress((void**)&pKH,  g_KH);
    cudaGetSymbolAddress((void**)&pKL,  g_KL);
    cudaGetSymbolAddress((void**)&pVH,  g_VH);
    cudaGetSymbolAddress((void**)&pVL,  g_VL);

    cudaFuncSetAttribute(flash_mma, cudaFuncAttributeMaxDynamicSharedMemorySize, FLASH_SMEM);
    cudaFuncSetAttribute(mma_gemm<0>, cudaFuncAttributeMaxDynamicSharedMemorySize, GEMM_SMEM);
    cudaFuncSetAttribute(mma_gemm<1>, cudaFuncAttributeMaxDynamicSharedMemorySize, GEMM_SMEM);

    // 0) single fused pre-round pass for x, Wqkv, Wout
    {
        const int n0 = (B_ * T_ * E_) / 4;
        const int n1 = (E_ * THREE_E) / 4;
        const int n2 = (E_ * E_) / 4;
        const int tot = n0 + n1 + n2;
        round_all<<<(tot + 255) / 256, 256>>>(
            (const float4*)x, (float4*)rx, n0,
            (const float4*)Wqkv, (float4*)rwq, n1,
            (const float4*)Wout, (float4*)rwo, n2);
    }

    // 1) QKV projection with fused Q/K split + V dense store
    mma_gemm<1><<<dim3(THREE_E / BN, (B_ * T_) / BM), NTHR, GEMM_SMEM>>>(
        B_ * T_, THREE_E, E_, rx, rwq, bqkv, nullptr,
        pQH, pQL, pKH, pKL, vbuf);

    // 1b) V transpose+split (smem-staged, fully coalesced)
    prep_v<<<dim3(T_ / 64, B_ * H_), 256>>>(vbuf, pVH, pVL);

    // 2) Flash attention (128-row q-tiles)
    flash_mma<<<dim3(T_ / 128, B_ * H_), 256, FLASH_SMEM>>>(
        pQH, pQL, pKH, pKL, pVH, pVL, att);

    // 3) Output projection (plain epilogue)
    mma_gemm<0><<<dim3(E_ / BN, (B_ * T_) / BM), NTHR, GEMM_SMEM>>>(
        B_ * T_, E_, E_, att, rwo, bout, out,
        nullptr, nullptr, nullptr, nullptr, nullptr);
}